// round 1
// baseline (speedup 1.0000x reference)
#include <cuda_runtime.h>

// Problem constants (fixed by the reference).
#define B_ 2
#define T_ 2048
#define E_ 1024
#define H_ 16
#define D_ 64

// Scratch (no allocations allowed): Q/K/V in [B,H,T,D], Y in [B,T,E].
__device__ float g_q[B_ * H_ * T_ * D_];
__device__ float g_k[B_ * H_ * T_ * D_];
__device__ float g_v[B_ * H_ * T_ * D_];
__device__ float g_y[B_ * T_ * E_];

// ---------------------------------------------------------------------------
// Tiled SGEMM, 128x128 tile, BK=8, 256 threads, 8x8 per-thread microtile.
// EPI==0: QKV epilogue (add bias, scatter into g_q/g_k/g_v, fold 1/sqrt(D)
//         into Q).
// EPI==1: plain epilogue C = A*B + bias, with A taken from g_y.
// ---------------------------------------------------------------------------
template <int EPI>
__global__ __launch_bounds__(256) void sgemm_kernel(const float* __restrict__ A,
                                                    const float* __restrict__ Bm,
                                                    const float* __restrict__ bias,
                                                    float* __restrict__ C,
                                                    int M, int N, int K) {
    __shared__ float As[8][128];
    __shared__ float Bs[8][128];

    const int tid  = threadIdx.x;
    const int row0 = blockIdx.y * 128;
    const int col0 = blockIdx.x * 128;

    const int aRow = tid >> 1;          // 0..127
    const int aCol = (tid & 1) * 4;     // 0 or 4
    const int bRow = tid >> 5;          // 0..7
    const int bCol = (tid & 31) * 4;    // 0..124
    const int ty   = tid >> 4;          // 0..15
    const int tx   = tid & 15;          // 0..15

    const float* Abase = (EPI == 1) ? g_y : A;
    const float* Aptr  = Abase + (size_t)(row0 + aRow) * K + aCol;
    const float* Bptr  = Bm + (size_t)bRow * N + col0 + bCol;

    float acc[8][8];
#pragma unroll
    for (int i = 0; i < 8; ++i)
#pragma unroll
        for (int j = 0; j < 8; ++j) acc[i][j] = 0.f;

    for (int k0 = 0; k0 < K; k0 += 8) {
        float4 av = *(const float4*)(Aptr + k0);
        float4 bv = *(const float4*)(Bptr + (size_t)k0 * N);
        __syncthreads();
        As[aCol + 0][aRow] = av.x;
        As[aCol + 1][aRow] = av.y;
        As[aCol + 2][aRow] = av.z;
        As[aCol + 3][aRow] = av.w;
        *(float4*)&Bs[bRow][bCol] = bv;
        __syncthreads();
#pragma unroll
        for (int kk = 0; kk < 8; ++kk) {
            float a[8], bb[8];
            *(float4*)&a[0]  = *(const float4*)&As[kk][ty * 8];
            *(float4*)&a[4]  = *(const float4*)&As[kk][ty * 8 + 4];
            *(float4*)&bb[0] = *(const float4*)&Bs[kk][tx * 8];
            *(float4*)&bb[4] = *(const float4*)&Bs[kk][tx * 8 + 4];
#pragma unroll
            for (int i = 0; i < 8; ++i)
#pragma unroll
                for (int j = 0; j < 8; ++j) acc[i][j] += a[i] * bb[j];
        }
    }

    // Epilogue
    float bvals[8];
#pragma unroll
    for (int j = 0; j < 8; ++j) bvals[j] = bias[col0 + tx * 8 + j];

#pragma unroll
    for (int i = 0; i < 8; ++i) {
        const int m = row0 + ty * 8 + i;
#pragma unroll
        for (int j = 0; j < 8; ++j) {
            const int n  = col0 + tx * 8 + j;
            const float v = acc[i][j] + bvals[j];
            if (EPI == 0) {
                const int which = n >> 10;       // 0=Q, 1=K, 2=V
                const int e = n & 1023;
                const int h = e >> 6;
                const int d = e & 63;
                const int b = m >> 11;           // m = b*T + t, T=2048
                const int t = m & 2047;
                const size_t idx =
                    (((size_t)(b * H_ + h) * T_ + t) << 6) + d;
                if (which == 0)      g_q[idx] = v * 0.125f;  // 1/sqrt(64)
                else if (which == 1) g_k[idx] = v;
                else                 g_v[idx] = v;
            } else {
                C[(size_t)m * N + n] = v;
            }
        }
    }
}

// ---------------------------------------------------------------------------
// Causal flash-style attention. One thread per query row. 128 queries per
// block; K/V tiles of 64 keys in shared memory. Online softmax with lazy
// accumulator rescale (rescale only on a new running max).
// Writes Y directly into [B,T,E] layout for the projection GEMM.
// ---------------------------------------------------------------------------
__global__ __launch_bounds__(128) void attn_kernel() {
    __shared__ float Ks[64 * 64];
    __shared__ float Vs[64 * 64];

    const int tid = threadIdx.x;
    const int q0  = blockIdx.x * 128;
    const int q   = q0 + tid;
    const int h   = blockIdx.y;
    const int b   = blockIdx.z;

    const size_t bh = (size_t)(b * H_ + h) * T_;
    const float* qp = g_q + (bh + q) * D_;
    const float* kp = g_k + bh * D_;
    const float* vp = g_v + bh * D_;

    float qr[64];
#pragma unroll
    for (int i = 0; i < 16; ++i) {
        float4 t4 = *(const float4*)(qp + i * 4);
        qr[i * 4 + 0] = t4.x;
        qr[i * 4 + 1] = t4.y;
        qr[i * 4 + 2] = t4.z;
        qr[i * 4 + 3] = t4.w;
    }

    float mx = -1e30f, l = 0.f;
    float acc[64];
#pragma unroll
    for (int d = 0; d < 64; ++d) acc[d] = 0.f;

    const int ntiles = (q0 + 128) >> 6;  // key tiles 0..ntiles-1 cover 0..q0+127
    for (int kt = 0; kt < ntiles; ++kt) {
        __syncthreads();
#pragma unroll
        for (int i = 0; i < 8; ++i) {
            const int lin = (i * 128 + tid) * 4;
            *(float4*)&Ks[lin] = *(const float4*)(kp + kt * 4096 + lin);
            *(float4*)&Vs[lin] = *(const float4*)(vp + kt * 4096 + lin);
        }
        __syncthreads();

        int jmax = q - kt * 64 + 1;
        if (jmax > 64) jmax = 64;
        for (int j = 0; j < jmax; ++j) {
            const float* kj = &Ks[j * 64];
            float s = 0.f;
#pragma unroll
            for (int i = 0; i < 16; ++i) {
                float4 k4 = *(const float4*)(kj + i * 4);
                s += qr[i * 4 + 0] * k4.x + qr[i * 4 + 1] * k4.y +
                     qr[i * 4 + 2] * k4.z + qr[i * 4 + 3] * k4.w;
            }
            const float* vj = &Vs[j * 64];
            if (s <= mx) {
                const float p = __expf(s - mx);
                l += p;
#pragma unroll
                for (int i = 0; i < 16; ++i) {
                    float4 v4 = *(const float4*)(vj + i * 4);
                    acc[i * 4 + 0] += p * v4.x;
                    acc[i * 4 + 1] += p * v4.y;
                    acc[i * 4 + 2] += p * v4.z;
                    acc[i * 4 + 3] += p * v4.w;
                }
            } else {
                const float r = __expf(mx - s);
                mx = s;
                l = l * r + 1.f;
#pragma unroll
                for (int i = 0; i < 16; ++i) {
                    float4 v4 = *(const float4*)(vj + i * 4);
                    acc[i * 4 + 0] = acc[i * 4 + 0] * r + v4.x;
                    acc[i * 4 + 1] = acc[i * 4 + 1] * r + v4.y;
                    acc[i * 4 + 2] = acc[i * 4 + 2] * r + v4.z;
                    acc[i * 4 + 3] = acc[i * 4 + 3] * r + v4.w;
                }
            }
        }
    }

    const float inv = 1.f / l;
    float* yp = g_y + ((size_t)(b * T_) + q) * E_ + h * D_;
#pragma unroll
    for (int i = 0; i < 16; ++i) {
        float4 o;
        o.x = acc[i * 4 + 0] * inv;
        o.y = acc[i * 4 + 1] * inv;
        o.z = acc[i * 4 + 2] * inv;
        o.w = acc[i * 4 + 3] * inv;
        *(float4*)(yp + i * 4) = o;
    }
}

// ---------------------------------------------------------------------------
// Launch: QKV GEMM -> attention -> projection GEMM (same stream, serialized).
// ---------------------------------------------------------------------------
extern "C" void kernel_launch(void* const* d_in, const int* in_sizes, int n_in,
                              void* d_out, int out_size) {
    const float* x      = (const float*)d_in[0];
    const float* W_attn = (const float*)d_in[1];
    const float* b_attn = (const float*)d_in[2];
    const float* W_proj = (const float*)d_in[3];
    const float* b_proj = (const float*)d_in[4];
    float* out = (float*)d_out;

    const int M = B_ * T_;   // 4096

    // 1) QKV = x @ W_attn + b_attn, scattered into g_q/g_k/g_v
    {
        dim3 grid(3 * E_ / 128, M / 128);  // (24, 32)
        sgemm_kernel<0><<<grid, 256>>>(x, W_attn, b_attn, nullptr,
                                       M, 3 * E_, E_);
    }
    // 2) causal attention -> g_y [B,T,E]
    {
        dim3 grid(T_ / 128, H_, B_);       // (16, 16, 2)
        attn_kernel<<<grid, 128>>>();
    }
    // 3) out = g_y @ W_proj + b_proj
    {
        dim3 grid(E_ / 128, M / 128);      // (8, 32)
        sgemm_kernel<1><<<grid, 256>>>(nullptr, W_proj, b_proj, out,
                                       M, E_, E_);
    }
}

// round 7
// speedup vs baseline: 1.5748x; 1.5748x over previous
#include <cuda_runtime.h>
#include <cuda_fp16.h>
#include <cstdint>

// Problem constants (fixed by the reference).
#define B_ 2
#define T_ 2048
#define E_ 1024
#define H_ 16
#define D_ 64
#define M_TOT 4096   // B*T
#define K_TOT 1024   // E

// ---------------------------------------------------------------------------
// Device scratch — EXACTLY the R1 set (64 MB fp32, proven to pass).
// NEVER passed as kernel arguments (host-side shadow address triggers the
// 128MiB UM-migration delta that failed R3/R4/R6) — referenced in device
// code only.
// ---------------------------------------------------------------------------
__device__ float g_q[B_ * H_ * T_ * D_];
__device__ float g_k[B_ * H_ * T_ * D_];
__device__ float g_v[B_ * H_ * T_ * D_];
__device__ float g_y[B_ * T_ * E_];

// ---------------------------------------------------------------------------
// PTX helpers (family-generic ISA: ldmatrix, mma.sync only).
// ---------------------------------------------------------------------------
__device__ __forceinline__ uint32_t s2u(const void* p) {
    uint32_t a;
    asm("{ .reg .u64 t; cvta.to.shared.u64 t, %1; cvt.u32.u64 %0, t; }"
        : "=r"(a) : "l"(p));
    return a;
}

// Pack two fp32 into one uint32 of two fp16 (round-to-nearest).
__device__ __forceinline__ uint32_t cvt2(float lo, float hi) {
    __half2 h = __floats2half2_rn(lo, hi);
    return *reinterpret_cast<uint32_t*>(&h);
}

__device__ __forceinline__ void ldsm_x4(uint32_t* r, uint32_t addr) {
    asm volatile("ldmatrix.sync.aligned.m8n8.x4.shared.b16 {%0,%1,%2,%3}, [%4];"
                 : "=r"(r[0]), "=r"(r[1]), "=r"(r[2]), "=r"(r[3]) : "r"(addr));
}

__device__ __forceinline__ void ldsm_x2t(uint32_t* r, uint32_t addr) {
    asm volatile("ldmatrix.sync.aligned.m8n8.x2.trans.shared.b16 {%0,%1}, [%2];"
                 : "=r"(r[0]), "=r"(r[1]) : "r"(addr));
}

__device__ __forceinline__ void mma_f16(float* c, const uint32_t* a, const uint32_t* b) {
    asm volatile(
        "mma.sync.aligned.m16n8k16.row.col.f32.f16.f16.f32 "
        "{%0,%1,%2,%3}, {%4,%5,%6,%7}, {%8,%9}, {%0,%1,%2,%3};"
        : "+f"(c[0]), "+f"(c[1]), "+f"(c[2]), "+f"(c[3])
        : "r"(a[0]), "r"(a[1]), "r"(a[2]), "r"(a[3]), "r"(b[0]), "r"(b[1]));
}

// FFMA-only exp for x <= 0 (avoids MUFU, whose chip throughput is tiny).
__device__ __forceinline__ float fexp(float x) {
    float t = x * 1.4426950408889634f;        // log2(e)
    t = fmaxf(t, -126.0f);
    float z = __fadd_rn(t, 12582912.0f);      // round-to-nearest-int magic
    float r = __fadd_rn(z, -12582912.0f);
    float f = t - r;                          // f in [-0.5, 0.5]
    int   e = (__float_as_int(z) << 23) + 0x3F800000;  // 2^round(t)
    float p = 0.0013333558f;
    p = fmaf(p, f, 0.0096181291f);
    p = fmaf(p, f, 0.0555041087f);
    p = fmaf(p, f, 0.2402265070f);
    p = fmaf(p, f, 0.6931471806f);
    p = fmaf(p, f, 1.0f);
    return __int_as_float(e) * p;
}

// ---------------------------------------------------------------------------
// fp16 mma.sync GEMM with in-kernel fp32->fp16 conversion.
//   C[M=4096, N] = A[4096, 1024] @ W[1024, N]  (+ bias)
// A fp32 row-major (EPI==0: the Ain argument = x; EPI==1: g_y, resolved in
// DEVICE code). W fp32 row-major ([K][N] -> B fragments via ldmatrix.trans).
// CTA tile 128x128, BK=32, 256 threads (8 warps, 64x32 warp tiles).
// Static smem 16KB. EPI==0: QKV scatter (+bias, Q*0.125) to g_q/g_k/g_v.
// EPI==1: Cout = ... + bias.
// ---------------------------------------------------------------------------
template <int EPI>
__global__ __launch_bounds__(256) void hgemm_kernel(
    const float* __restrict__ Ain, const float* __restrict__ W,
    const float* __restrict__ bias, float* __restrict__ Cout, int N) {
    __shared__ __align__(16) __half As[128 * 32];   // 8 KB
    __shared__ __align__(16) __half Bs[32 * 128];   // 8 KB

    const float* A = (EPI == 1) ? (const float*)g_y : Ain;

    const uint32_t aBase = s2u(As);
    const uint32_t bBase = s2u(Bs);
    const int tid = threadIdx.x;
    const int lane = tid & 31;
    const int warp = tid >> 5;
    const int wm = warp >> 2;            // 0..1
    const int wn = warp & 3;             // 0..3
    const int row0 = blockIdx.y * 128;
    const int col0 = blockIdx.x * 128;

    // A store mapping: rows ar0 and ar0+64, 16B half-chunk ac within 64B row.
    const int ar0 = tid >> 2;            // 0..63
    const int ac  = tid & 3;             // 16B chunk within 64B row
    // B store mapping: k = tid>>3 (0..31), chunks bc and bc+8 of 16.
    const int bk  = tid >> 3;
    const int bc  = tid & 7;

    float acc[4][4][4];
#pragma unroll
    for (int i = 0; i < 4; ++i)
#pragma unroll
        for (int j = 0; j < 4; ++j)
#pragma unroll
            for (int k = 0; k < 4; ++k) acc[i][j][k] = 0.f;

    for (int kc = 0; kc < K_TOT / 32; ++kc) {
        const int k0 = kc * 32;

        // ---- global loads (fp32) ----
        float4 a0a = *(const float4*)(A + (size_t)(row0 + ar0) * K_TOT + k0 + ac * 8);
        float4 a0b = *(const float4*)(A + (size_t)(row0 + ar0) * K_TOT + k0 + ac * 8 + 4);
        float4 a1a = *(const float4*)(A + (size_t)(row0 + ar0 + 64) * K_TOT + k0 + ac * 8);
        float4 a1b = *(const float4*)(A + (size_t)(row0 + ar0 + 64) * K_TOT + k0 + ac * 8 + 4);
        float4 b0a = *(const float4*)(W + (size_t)(k0 + bk) * N + col0 + bc * 8);
        float4 b0b = *(const float4*)(W + (size_t)(k0 + bk) * N + col0 + bc * 8 + 4);
        float4 b1a = *(const float4*)(W + (size_t)(k0 + bk) * N + col0 + (bc + 8) * 8);
        float4 b1b = *(const float4*)(W + (size_t)(k0 + bk) * N + col0 + (bc + 8) * 8 + 4);

        __syncthreads();

        // ---- convert + store to swizzled smem ----
        {
            uint4 u;
            u.x = cvt2(a0a.x, a0a.y);
            u.y = cvt2(a0a.z, a0a.w);
            u.z = cvt2(a0b.x, a0b.y);
            u.w = cvt2(a0b.z, a0b.w);
            *(uint4*)((char*)As + ar0 * 64 + ((ac ^ (ar0 & 3)) << 4)) = u;
            u.x = cvt2(a1a.x, a1a.y);
            u.y = cvt2(a1a.z, a1a.w);
            u.z = cvt2(a1b.x, a1b.y);
            u.w = cvt2(a1b.z, a1b.w);
            *(uint4*)((char*)As + (ar0 + 64) * 64 + ((ac ^ ((ar0 + 64) & 3)) << 4)) = u;
            u.x = cvt2(b0a.x, b0a.y);
            u.y = cvt2(b0a.z, b0a.w);
            u.z = cvt2(b0b.x, b0b.y);
            u.w = cvt2(b0b.z, b0b.w);
            *(uint4*)((char*)Bs + bk * 256 + ((bc ^ (bk & 7)) << 4)) = u;
            u.x = cvt2(b1a.x, b1a.y);
            u.y = cvt2(b1a.z, b1a.w);
            u.z = cvt2(b1b.x, b1b.y);
            u.w = cvt2(b1b.z, b1b.w);
            *(uint4*)((char*)Bs + bk * 256 + (((bc + 8) ^ (bk & 7)) << 4)) = u;
        }
        __syncthreads();

        // ---- mma: 2 k-steps of 16 ----
#pragma unroll
        for (int ks = 0; ks < 2; ++ks) {
            uint32_t bf[4][2];
#pragma unroll
            for (int nt = 0; nt < 4; ++nt) {
                const int n0 = wn * 32 + nt * 8;
                const int l = lane & 15;
                const int krow = ks * 16 + (l >> 3) * 8 + (l & 7);
                ldsm_x2t(bf[nt], bBase + krow * 256 + (((n0 >> 3) ^ (krow & 7)) << 4));
            }
#pragma unroll
            for (int mt = 0; mt < 4; ++mt) {
                uint32_t af[4];
                const int mrow = wm * 64 + mt * 16 + (lane & 15);
                const int chnk = ks * 2 + (lane >> 4);
                ldsm_x4(af, aBase + mrow * 64 + ((chnk ^ (mrow & 3)) << 4));
#pragma unroll
                for (int nt = 0; nt < 4; ++nt) mma_f16(acc[mt][nt], af, bf[nt]);
            }
        }
    }

    // ---- epilogue ----
#pragma unroll
    for (int mt = 0; mt < 4; ++mt) {
#pragma unroll
        for (int nt = 0; nt < 4; ++nt) {
            const int m_base = row0 + wm * 64 + mt * 16 + (lane >> 2);
            const int n_base = col0 + wn * 32 + nt * 8 + (lane & 3) * 2;
#pragma unroll
            for (int e = 0; e < 4; ++e) {
                const int m = m_base + (e >> 1) * 8;
                const int n = n_base + (e & 1);
                const float v = acc[mt][nt][e] + __ldg(bias + n);
                if (EPI == 0) {
                    const int which = n >> 10;   // 0=Q,1=K,2=V (uniform per CTA)
                    const int ei = n & 1023;
                    const int h = ei >> 6;
                    const int d = ei & 63;
                    const int b = m >> 11;
                    const int t = m & 2047;
                    const size_t idx = (((size_t)(b * H_ + h) * T_ + t) << 6) + d;
                    if (which == 0)      g_q[idx] = v * 0.125f;
                    else if (which == 1) g_k[idx] = v;
                    else                 g_v[idx] = v;
                } else {
                    Cout[(size_t)m * E_ + n] = v;
                }
            }
        }
    }
}

// ---------------------------------------------------------------------------
// Causal flash-style attention — R1's proven kernel, with __expf -> fexp.
// ---------------------------------------------------------------------------
__global__ __launch_bounds__(128) void attn_kernel() {
    __shared__ float Ks[64 * 64];
    __shared__ float Vs[64 * 64];

    const int tid = threadIdx.x;
    const int q0  = blockIdx.x * 128;
    const int q   = q0 + tid;
    const int h   = blockIdx.y;
    const int b   = blockIdx.z;

    const size_t bh = (size_t)(b * H_ + h) * T_;
    const float* qp = g_q + (bh + q) * D_;
    const float* kp = g_k + bh * D_;
    const float* vp = g_v + bh * D_;

    float qr[64];
#pragma unroll
    for (int i = 0; i < 16; ++i) {
        float4 t4 = *(const float4*)(qp + i * 4);
        qr[i * 4 + 0] = t4.x; qr[i * 4 + 1] = t4.y;
        qr[i * 4 + 2] = t4.z; qr[i * 4 + 3] = t4.w;
    }

    float mx = -1e30f, l = 0.f;
    float acc[64];
#pragma unroll
    for (int d = 0; d < 64; ++d) acc[d] = 0.f;

    const int ntiles = (q0 + 128) >> 6;
    for (int kt = 0; kt < ntiles; ++kt) {
        __syncthreads();
#pragma unroll
        for (int i = 0; i < 8; ++i) {
            const int lin = (i * 128 + tid) * 4;
            *(float4*)&Ks[lin] = *(const float4*)(kp + kt * 4096 + lin);
            *(float4*)&Vs[lin] = *(const float4*)(vp + kt * 4096 + lin);
        }
        __syncthreads();

        int jmax = q - kt * 64 + 1;
        if (jmax > 64) jmax = 64;
        for (int j = 0; j < jmax; ++j) {
            const float* kj = &Ks[j * 64];
            float s = 0.f;
#pragma unroll
            for (int i = 0; i < 16; ++i) {
                float4 k4 = *(const float4*)(kj + i * 4);
                s += qr[i * 4 + 0] * k4.x + qr[i * 4 + 1] * k4.y +
                     qr[i * 4 + 2] * k4.z + qr[i * 4 + 3] * k4.w;
            }
            const float* vj = &Vs[j * 64];
            if (s <= mx) {
                const float p = fexp(s - mx);
                l += p;
#pragma unroll
                for (int i = 0; i < 16; ++i) {
                    float4 v4 = *(const float4*)(vj + i * 4);
                    acc[i * 4 + 0] += p * v4.x;
                    acc[i * 4 + 1] += p * v4.y;
                    acc[i * 4 + 2] += p * v4.z;
                    acc[i * 4 + 3] += p * v4.w;
                }
            } else {
                const float rr = fexp(mx - s);
                mx = s;
                l = l * rr + 1.f;
#pragma unroll
                for (int i = 0; i < 16; ++i) {
                    float4 v4 = *(const float4*)(vj + i * 4);
                    acc[i * 4 + 0] = acc[i * 4 + 0] * rr + v4.x;
                    acc[i * 4 + 1] = acc[i * 4 + 1] * rr + v4.y;
                    acc[i * 4 + 2] = acc[i * 4 + 2] * rr + v4.z;
                    acc[i * 4 + 3] = acc[i * 4 + 3] * rr + v4.w;
                }
            }
        }
    }

    const float inv = 1.f / l;
    float* yp = g_y + ((size_t)(b * T_) + q) * E_ + h * D_;
#pragma unroll
    for (int i = 0; i < 16; ++i) {
        float4 o;
        o.x = acc[i * 4 + 0] * inv;
        o.y = acc[i * 4 + 1] * inv;
        o.z = acc[i * 4 + 2] * inv;
        o.w = acc[i * 4 + 3] * inv;
        *(float4*)(yp + i * 4) = o;
    }
}

// ---------------------------------------------------------------------------
// Launch: QKV GEMM -> attention -> projection GEMM.
// Only harness-provided pointers cross the host->kernel boundary.
// ---------------------------------------------------------------------------
extern "C" void kernel_launch(void* const* d_in, const int* in_sizes, int n_in,
                              void* d_out, int out_size) {
    const float* x      = (const float*)d_in[0];
    const float* W_attn = (const float*)d_in[1];
    const float* b_attn = (const float*)d_in[2];
    const float* W_proj = (const float*)d_in[3];
    const float* b_proj = (const float*)d_in[4];
    float* out = (float*)d_out;

    // 1) QKV = x @ W_attn + b_attn  (fp16 mma, scatter into g_q/g_k/g_v)
    {
        dim3 grid(3 * E_ / 128, M_TOT / 128);  // (24, 32)
        hgemm_kernel<0><<<grid, 256>>>(x, W_attn, b_attn, nullptr, 3 * E_);
    }
    // 2) causal attention -> g_y
    {
        dim3 grid(T_ / 128, H_, B_);           // (16, 16, 2)
        attn_kernel<<<grid, 128>>>();
    }
    // 3) out = g_y @ W_proj + b_proj  (A = g_y resolved in device code)
    {
        dim3 grid(E_ / 128, M_TOT / 128);      // (8, 32)
        hgemm_kernel<1><<<grid, 256>>>(nullptr, W_proj, b_proj, out, E_);
    }
}

// round 9
// speedup vs baseline: 4.9482x; 3.1421x over previous
#include <cuda_runtime.h>
#include <cuda_fp16.h>
#include <cstdint>

// Problem constants (fixed by the reference).
#define B_ 2
#define T_ 2048
#define E_ 1024
#define H_ 16
#define D_ 64
#define M_TOT 4096   // B*T
#define K_TOT 1024   // E

// ---------------------------------------------------------------------------
// Device scratch — R1 set (64 MB fp32, proven). NEVER passed as kernel
// arguments (device-symbol-as-arg triggered the 128MiB UM delta).
// ---------------------------------------------------------------------------
__device__ float g_q[B_ * H_ * T_ * D_];
__device__ float g_k[B_ * H_ * T_ * D_];
__device__ float g_v[B_ * H_ * T_ * D_];
__device__ float g_y[B_ * T_ * E_];

// ---------------------------------------------------------------------------
// PTX helpers (family-generic ISA: ldmatrix, mma.sync only).
// ---------------------------------------------------------------------------
__device__ __forceinline__ uint32_t s2u(const void* p) {
    uint32_t a;
    asm("{ .reg .u64 t; cvta.to.shared.u64 t, %1; cvt.u32.u64 %0, t; }"
        : "=r"(a) : "l"(p));
    return a;
}

__device__ __forceinline__ uint32_t cvt2(float lo, float hi) {
    __half2 h = __floats2half2_rn(lo, hi);
    return *reinterpret_cast<uint32_t*>(&h);
}

__device__ __forceinline__ void ldsm_x4(uint32_t* r, uint32_t addr) {
    asm volatile("ldmatrix.sync.aligned.m8n8.x4.shared.b16 {%0,%1,%2,%3}, [%4];"
                 : "=r"(r[0]), "=r"(r[1]), "=r"(r[2]), "=r"(r[3]) : "r"(addr));
}

__device__ __forceinline__ void ldsm_x4t(uint32_t* r, uint32_t addr) {
    asm volatile("ldmatrix.sync.aligned.m8n8.x4.trans.shared.b16 {%0,%1,%2,%3}, [%4];"
                 : "=r"(r[0]), "=r"(r[1]), "=r"(r[2]), "=r"(r[3]) : "r"(addr));
}

__device__ __forceinline__ void ldsm_x2t(uint32_t* r, uint32_t addr) {
    asm volatile("ldmatrix.sync.aligned.m8n8.x2.trans.shared.b16 {%0,%1}, [%2];"
                 : "=r"(r[0]), "=r"(r[1]) : "r"(addr));
}

__device__ __forceinline__ void mma_f16(float* c, const uint32_t* a, const uint32_t* b) {
    asm volatile(
        "mma.sync.aligned.m16n8k16.row.col.f32.f16.f16.f32 "
        "{%0,%1,%2,%3}, {%4,%5,%6,%7}, {%8,%9}, {%0,%1,%2,%3};"
        : "+f"(c[0]), "+f"(c[1]), "+f"(c[2]), "+f"(c[3])
        : "r"(a[0]), "r"(a[1]), "r"(a[2]), "r"(a[3]), "r"(b[0]), "r"(b[1]));
}

// FFMA-only exp for x <= 0.
__device__ __forceinline__ float fexp(float x) {
    float t = x * 1.4426950408889634f;
    t = fmaxf(t, -126.0f);
    float z = __fadd_rn(t, 12582912.0f);
    float r = __fadd_rn(z, -12582912.0f);
    float f = t - r;
    int   e = (__float_as_int(z) << 23) + 0x3F800000;
    float p = 0.0013333558f;
    p = fmaf(p, f, 0.0096181291f);
    p = fmaf(p, f, 0.0555041087f);
    p = fmaf(p, f, 0.2402265070f);
    p = fmaf(p, f, 0.6931471806f);
    p = fmaf(p, f, 1.0f);
    return __int_as_float(e) * p;
}

// ---------------------------------------------------------------------------
// fp16 mma.sync GEMM (unchanged from the passing R7 kernel).
// ---------------------------------------------------------------------------
template <int EPI>
__global__ __launch_bounds__(256) void hgemm_kernel(
    const float* __restrict__ Ain, const float* __restrict__ W,
    const float* __restrict__ bias, float* __restrict__ Cout, int N) {
    __shared__ __align__(16) __half As[128 * 32];
    __shared__ __align__(16) __half Bs[32 * 128];

    const float* A = (EPI == 1) ? (const float*)g_y : Ain;

    const uint32_t aBase = s2u(As);
    const uint32_t bBase = s2u(Bs);
    const int tid = threadIdx.x;
    const int lane = tid & 31;
    const int warp = tid >> 5;
    const int wm = warp >> 2;
    const int wn = warp & 3;
    const int row0 = blockIdx.y * 128;
    const int col0 = blockIdx.x * 128;

    const int ar0 = tid >> 2;
    const int ac  = tid & 3;
    const int bk  = tid >> 3;
    const int bc  = tid & 7;

    float acc[4][4][4];
#pragma unroll
    for (int i = 0; i < 4; ++i)
#pragma unroll
        for (int j = 0; j < 4; ++j)
#pragma unroll
            for (int k = 0; k < 4; ++k) acc[i][j][k] = 0.f;

    for (int kc = 0; kc < K_TOT / 32; ++kc) {
        const int k0 = kc * 32;

        float4 a0a = *(const float4*)(A + (size_t)(row0 + ar0) * K_TOT + k0 + ac * 8);
        float4 a0b = *(const float4*)(A + (size_t)(row0 + ar0) * K_TOT + k0 + ac * 8 + 4);
        float4 a1a = *(const float4*)(A + (size_t)(row0 + ar0 + 64) * K_TOT + k0 + ac * 8);
        float4 a1b = *(const float4*)(A + (size_t)(row0 + ar0 + 64) * K_TOT + k0 + ac * 8 + 4);
        float4 b0a = *(const float4*)(W + (size_t)(k0 + bk) * N + col0 + bc * 8);
        float4 b0b = *(const float4*)(W + (size_t)(k0 + bk) * N + col0 + bc * 8 + 4);
        float4 b1a = *(const float4*)(W + (size_t)(k0 + bk) * N + col0 + (bc + 8) * 8);
        float4 b1b = *(const float4*)(W + (size_t)(k0 + bk) * N + col0 + (bc + 8) * 8 + 4);

        __syncthreads();
        {
            uint4 u;
            u.x = cvt2(a0a.x, a0a.y); u.y = cvt2(a0a.z, a0a.w);
            u.z = cvt2(a0b.x, a0b.y); u.w = cvt2(a0b.z, a0b.w);
            *(uint4*)((char*)As + ar0 * 64 + ((ac ^ (ar0 & 3)) << 4)) = u;
            u.x = cvt2(a1a.x, a1a.y); u.y = cvt2(a1a.z, a1a.w);
            u.z = cvt2(a1b.x, a1b.y); u.w = cvt2(a1b.z, a1b.w);
            *(uint4*)((char*)As + (ar0 + 64) * 64 + ((ac ^ ((ar0 + 64) & 3)) << 4)) = u;
            u.x = cvt2(b0a.x, b0a.y); u.y = cvt2(b0a.z, b0a.w);
            u.z = cvt2(b0b.x, b0b.y); u.w = cvt2(b0b.z, b0b.w);
            *(uint4*)((char*)Bs + bk * 256 + ((bc ^ (bk & 7)) << 4)) = u;
            u.x = cvt2(b1a.x, b1a.y); u.y = cvt2(b1a.z, b1a.w);
            u.z = cvt2(b1b.x, b1b.y); u.w = cvt2(b1b.z, b1b.w);
            *(uint4*)((char*)Bs + bk * 256 + (((bc + 8) ^ (bk & 7)) << 4)) = u;
        }
        __syncthreads();

#pragma unroll
        for (int ks = 0; ks < 2; ++ks) {
            uint32_t bf[4][2];
#pragma unroll
            for (int nt = 0; nt < 4; ++nt) {
                const int n0 = wn * 32 + nt * 8;
                const int l = lane & 15;
                const int krow = ks * 16 + (l >> 3) * 8 + (l & 7);
                ldsm_x2t(bf[nt], bBase + krow * 256 + (((n0 >> 3) ^ (krow & 7)) << 4));
            }
#pragma unroll
            for (int mt = 0; mt < 4; ++mt) {
                uint32_t af[4];
                const int mrow = wm * 64 + mt * 16 + (lane & 15);
                const int chnk = ks * 2 + (lane >> 4);
                ldsm_x4(af, aBase + mrow * 64 + ((chnk ^ (mrow & 3)) << 4));
#pragma unroll
                for (int nt = 0; nt < 4; ++nt) mma_f16(acc[mt][nt], af, bf[nt]);
            }
        }
    }

#pragma unroll
    for (int mt = 0; mt < 4; ++mt) {
#pragma unroll
        for (int nt = 0; nt < 4; ++nt) {
            const int m_base = row0 + wm * 64 + mt * 16 + (lane >> 2);
            const int n_base = col0 + wn * 32 + nt * 8 + (lane & 3) * 2;
#pragma unroll
            for (int e = 0; e < 4; ++e) {
                const int m = m_base + (e >> 1) * 8;
                const int n = n_base + (e & 1);
                const float v = acc[mt][nt][e] + __ldg(bias + n);
                if (EPI == 0) {
                    const int which = n >> 10;
                    const int ei = n & 1023;
                    const int h = ei >> 6;
                    const int d = ei & 63;
                    const int b = m >> 11;
                    const int t = m & 2047;
                    const size_t idx = (((size_t)(b * H_ + h) * T_ + t) << 6) + d;
                    if (which == 0)      g_q[idx] = v * 0.125f;
                    else if (which == 1) g_k[idx] = v;
                    else                 g_v[idx] = v;
                } else {
                    Cout[(size_t)m * E_ + n] = v;
                }
            }
        }
    }
}

// ---------------------------------------------------------------------------
// Tensor-core causal flash attention (FA2 style, mma.sync fp16, fp32 softmax).
// 8 warps, 128-query tile (16 rows/warp), 64-key KV tiles in fp16 smem.
// ---------------------------------------------------------------------------
__global__ __launch_bounds__(256) void fattn_kernel() {
    __shared__ __align__(16) __half Ks[64 * 64];   // [key][d] fp16, swizzled
    __shared__ __align__(16) __half Vs[64 * 64];

    const int tid = threadIdx.x, lane = tid & 31, w = tid >> 5;
    const int q0 = blockIdx.x * 128;
    const int h = blockIdx.y, b = blockIdx.z;
    const size_t bh = (size_t)(b * H_ + h) * T_;
    const int wq = q0 + w * 16;                    // warp's first query row
    const uint32_t ksB = s2u(Ks), vsB = s2u(Vs);

    // Q fragments (already scaled by 1/sqrt(D)); A-layout for m16n8k16.
    uint32_t aq[4][4];
    {
        const float* qr0 = g_q + (bh + wq + (lane >> 2)) * D_;
        const float* qr1 = qr0 + 8 * D_;
#pragma unroll
        for (int ks = 0; ks < 4; ++ks) {
            const int c = ks * 16 + (lane & 3) * 2;
            aq[ks][0] = cvt2(qr0[c], qr0[c + 1]);
            aq[ks][1] = cvt2(qr1[c], qr1[c + 1]);
            aq[ks][2] = cvt2(qr0[c + 8], qr0[c + 9]);
            aq[ks][3] = cvt2(qr1[c + 8], qr1[c + 9]);
        }
    }

    float o[8][4];
#pragma unroll
    for (int i = 0; i < 8; ++i)
#pragma unroll
        for (int e = 0; e < 4; ++e) o[i][e] = 0.f;
    float m0 = -1e30f, m1 = -1e30f, l0 = 0.f, l1 = 0.f;

    const int ntiles = 2 * blockIdx.x + 2;
    for (int kt = 0; kt < ntiles; ++kt) {
        __syncthreads();
        // Load K/V 64x64 tile, fp32 -> fp16, XOR-swizzled (chunk ^ (row&7)).
#pragma unroll
        for (int i = 0; i < 2; ++i) {
            const int cid = i * 256 + tid;          // 0..511
            const int key = cid >> 3, ch = cid & 7;
            const float* ksrc = g_k + (bh + kt * 64 + key) * D_ + ch * 8;
            const float* vsrc = g_v + (bh + kt * 64 + key) * D_ + ch * 8;
            float4 k0 = *(const float4*)ksrc, k1 = *(const float4*)(ksrc + 4);
            float4 v0 = *(const float4*)vsrc, v1 = *(const float4*)(vsrc + 4);
            uint4 u;
            u.x = cvt2(k0.x, k0.y); u.y = cvt2(k0.z, k0.w);
            u.z = cvt2(k1.x, k1.y); u.w = cvt2(k1.z, k1.w);
            *(uint4*)((char*)Ks + key * 128 + ((ch ^ (key & 7)) << 4)) = u;
            u.x = cvt2(v0.x, v0.y); u.y = cvt2(v0.z, v0.w);
            u.z = cvt2(v1.x, v1.y); u.w = cvt2(v1.z, v1.w);
            *(uint4*)((char*)Vs + key * 128 + ((ch ^ (key & 7)) << 4)) = u;
        }
        __syncthreads();
        if (kt * 64 > wq + 15) continue;   // tile entirely above diagonal

        // ---- S = Q K^T  (16 x 64 per warp) ----
        float s[8][4];
#pragma unroll
        for (int nt = 0; nt < 8; ++nt)
#pragma unroll
            for (int e = 0; e < 4; ++e) s[nt][e] = 0.f;
#pragma unroll
        for (int p = 0; p < 2; ++p) {
#pragma unroll
            for (int nt = 0; nt < 8; ++nt) {
                uint32_t bk4[4];
                const int key = nt * 8 + (lane & 7);
                const int ch = p * 4 + (lane >> 3);
                ldsm_x4(bk4, ksB + key * 128 + ((ch ^ (key & 7)) << 4));
                mma_f16(s[nt], aq[2 * p], bk4);
                mma_f16(s[nt], aq[2 * p + 1], bk4 + 2);
            }
        }

        // ---- causal mask (only tiles that can cross the diagonal) ----
        if (kt * 64 + 63 > wq) {
            const int r0a = wq + (lane >> 2);
            const int colb = kt * 64 + (lane & 3) * 2;
#pragma unroll
            for (int nt = 0; nt < 8; ++nt) {
                const int c0 = colb + nt * 8;
                if (c0 > r0a)         s[nt][0] = -1e30f;
                if (c0 + 1 > r0a)     s[nt][1] = -1e30f;
                if (c0 > r0a + 8)     s[nt][2] = -1e30f;
                if (c0 + 1 > r0a + 8) s[nt][3] = -1e30f;
            }
        }

        // ---- online softmax (rows r0=lane>>2, r1=r0+8) ----
        float mx0 = -1e30f, mx1 = -1e30f;
#pragma unroll
        for (int nt = 0; nt < 8; ++nt) {
            mx0 = fmaxf(mx0, fmaxf(s[nt][0], s[nt][1]));
            mx1 = fmaxf(mx1, fmaxf(s[nt][2], s[nt][3]));
        }
        mx0 = fmaxf(mx0, __shfl_xor_sync(0xffffffffu, mx0, 1));
        mx0 = fmaxf(mx0, __shfl_xor_sync(0xffffffffu, mx0, 2));
        mx1 = fmaxf(mx1, __shfl_xor_sync(0xffffffffu, mx1, 1));
        mx1 = fmaxf(mx1, __shfl_xor_sync(0xffffffffu, mx1, 2));
        const float mn0 = fmaxf(m0, mx0), mn1 = fmaxf(m1, mx1);
        const float sc0 = fexp(m0 - mn0), sc1 = fexp(m1 - mn1);
        m0 = mn0; m1 = mn1;
        float rs0 = 0.f, rs1 = 0.f;
#pragma unroll
        for (int nt = 0; nt < 8; ++nt) {
            s[nt][0] = fexp(s[nt][0] - mn0);
            s[nt][1] = fexp(s[nt][1] - mn0);
            s[nt][2] = fexp(s[nt][2] - mn1);
            s[nt][3] = fexp(s[nt][3] - mn1);
            rs0 += s[nt][0] + s[nt][1];
            rs1 += s[nt][2] + s[nt][3];
        }
        rs0 += __shfl_xor_sync(0xffffffffu, rs0, 1);
        rs0 += __shfl_xor_sync(0xffffffffu, rs0, 2);
        rs1 += __shfl_xor_sync(0xffffffffu, rs1, 1);
        rs1 += __shfl_xor_sync(0xffffffffu, rs1, 2);
        l0 = l0 * sc0 + rs0;
        l1 = l1 * sc1 + rs1;
#pragma unroll
        for (int nt = 0; nt < 8; ++nt) {
            o[nt][0] *= sc0; o[nt][1] *= sc0;
            o[nt][2] *= sc1; o[nt][3] *= sc1;
        }

        // ---- pack P to A-fragments (C-layout == A-layout trick) ----
        uint32_t pa[4][4];
#pragma unroll
        for (int kp = 0; kp < 4; ++kp) {
            pa[kp][0] = cvt2(s[2 * kp][0],     s[2 * kp][1]);
            pa[kp][1] = cvt2(s[2 * kp][2],     s[2 * kp][3]);
            pa[kp][2] = cvt2(s[2 * kp + 1][0], s[2 * kp + 1][1]);
            pa[kp][3] = cvt2(s[2 * kp + 1][2], s[2 * kp + 1][3]);
        }

        // ---- O += P V  (V via ldmatrix.trans: [k=key][n=d] storage) ----
#pragma unroll
        for (int p2 = 0; p2 < 2; ++p2) {
#pragma unroll
            for (int nt2 = 0; nt2 < 8; ++nt2) {
                uint32_t bv[4];
                const int key = p2 * 32 + (lane >> 3) * 8 + (lane & 7);
                ldsm_x4t(bv, vsB + key * 128 + ((nt2 ^ (key & 7)) << 4));
                mma_f16(o[nt2], pa[2 * p2], bv);
                mma_f16(o[nt2], pa[2 * p2 + 1], bv + 2);
            }
        }
    }

    // ---- finalize + write y [B,T,E] ----
    const float inv0 = 1.f / l0, inv1 = 1.f / l1;
    float* y0 = g_y + ((size_t)(b * T_) + wq + (lane >> 2)) * E_ + h * D_ + (lane & 3) * 2;
    float* y1 = y0 + 8 * E_;
#pragma unroll
    for (int nt = 0; nt < 8; ++nt) {
        *(float2*)(y0 + nt * 8) = make_float2(o[nt][0] * inv0, o[nt][1] * inv0);
        *(float2*)(y1 + nt * 8) = make_float2(o[nt][2] * inv1, o[nt][3] * inv1);
    }
}

// ---------------------------------------------------------------------------
// Launch: QKV GEMM -> attention -> projection GEMM.
// ---------------------------------------------------------------------------
extern "C" void kernel_launch(void* const* d_in, const int* in_sizes, int n_in,
                              void* d_out, int out_size) {
    const float* x      = (const float*)d_in[0];
    const float* W_attn = (const float*)d_in[1];
    const float* b_attn = (const float*)d_in[2];
    const float* W_proj = (const float*)d_in[3];
    const float* b_proj = (const float*)d_in[4];
    float* out = (float*)d_out;

    // 1) QKV = x @ W_attn + b_attn
    {
        dim3 grid(3 * E_ / 128, M_TOT / 128);
        hgemm_kernel<0><<<grid, 256>>>(x, W_attn, b_attn, nullptr, 3 * E_);
    }
    // 2) causal attention -> g_y (tensor-core flash attention)
    {
        dim3 grid(T_ / 128, H_, B_);           // (16, 16, 2)
        fattn_kernel<<<grid, 256>>>();
    }
    // 3) out = g_y @ W_proj + b_proj
    {
        dim3 grid(E_ / 128, M_TOT / 128);
        hgemm_kernel<1><<<grid, 256>>>(nullptr, W_proj, b_proj, out, E_);
    }
}

// round 11
// speedup vs baseline: 5.6777x; 1.1474x over previous
#include <cuda_runtime.h>
#include <cuda_fp16.h>
#include <cstdint>

// Problem constants (fixed by the reference).
#define B_ 2
#define T_ 2048
#define E_ 1024
#define H_ 16
#define D_ 64
#define M_TOT 4096   // B*T
#define K_TOT 1024   // E

// ---------------------------------------------------------------------------
// Device scratch (48 MB fp16 total; < proven 64 MB). NEVER passed as kernel
// arguments (device-symbol-as-arg triggered the 128MiB UM delta in R3/4/6).
// ---------------------------------------------------------------------------
__device__ __half g_qh[B_ * H_ * T_ * D_];    // 8 MB
__device__ __half g_kh[B_ * H_ * T_ * D_];    // 8 MB
__device__ __half g_vh[B_ * H_ * T_ * D_];    // 8 MB
__device__ __half g_yh[M_TOT * E_];           // 8 MB
__device__ __half g_xh[M_TOT * K_TOT];        // 8 MB
__device__ __half g_wah[K_TOT * 3 * E_];      // 6 MB
__device__ __half g_wph[K_TOT * E_];          // 2 MB

// ---------------------------------------------------------------------------
// PTX helpers (family-generic ISA: ldmatrix, mma.sync only).
// ---------------------------------------------------------------------------
__device__ __forceinline__ uint32_t s2u(const void* p) {
    uint32_t a;
    asm("{ .reg .u64 t; cvta.to.shared.u64 t, %1; cvt.u32.u64 %0, t; }"
        : "=r"(a) : "l"(p));
    return a;
}

__device__ __forceinline__ uint32_t cvt2(float lo, float hi) {
    __half2 h = __floats2half2_rn(lo, hi);
    return *reinterpret_cast<uint32_t*>(&h);
}

__device__ __forceinline__ void ldsm_x4(uint32_t* r, uint32_t addr) {
    asm volatile("ldmatrix.sync.aligned.m8n8.x4.shared.b16 {%0,%1,%2,%3}, [%4];"
                 : "=r"(r[0]), "=r"(r[1]), "=r"(r[2]), "=r"(r[3]) : "r"(addr));
}

__device__ __forceinline__ void ldsm_x4t(uint32_t* r, uint32_t addr) {
    asm volatile("ldmatrix.sync.aligned.m8n8.x4.trans.shared.b16 {%0,%1,%2,%3}, [%4];"
                 : "=r"(r[0]), "=r"(r[1]), "=r"(r[2]), "=r"(r[3]) : "r"(addr));
}

__device__ __forceinline__ void ldsm_x2t(uint32_t* r, uint32_t addr) {
    asm volatile("ldmatrix.sync.aligned.m8n8.x2.trans.shared.b16 {%0,%1}, [%2];"
                 : "=r"(r[0]), "=r"(r[1]) : "r"(addr));
}

__device__ __forceinline__ void mma_f16(float* c, const uint32_t* a, const uint32_t* b) {
    asm volatile(
        "mma.sync.aligned.m16n8k16.row.col.f32.f16.f16.f32 "
        "{%0,%1,%2,%3}, {%4,%5,%6,%7}, {%8,%9}, {%0,%1,%2,%3};"
        : "+f"(c[0]), "+f"(c[1]), "+f"(c[2]), "+f"(c[3])
        : "r"(a[0]), "r"(a[1]), "r"(a[2]), "r"(a[3]), "r"(b[0]), "r"(b[1]));
}

// FFMA-only exp for x <= 0.
__device__ __forceinline__ float fexp(float x) {
    float t = x * 1.4426950408889634f;
    t = fmaxf(t, -126.0f);
    float z = __fadd_rn(t, 12582912.0f);
    float r = __fadd_rn(z, -12582912.0f);
    float f = t - r;
    int   e = (__float_as_int(z) << 23) + 0x3F800000;
    float p = 0.0013333558f;
    p = fmaf(p, f, 0.0096181291f);
    p = fmaf(p, f, 0.0555041087f);
    p = fmaf(p, f, 0.2402265070f);
    p = fmaf(p, f, 0.6931471806f);
    p = fmaf(p, f, 1.0f);
    return __int_as_float(e) * p;
}

// ---------------------------------------------------------------------------
// Prep: fp32 -> fp16 for x, W_attn, W_proj (outputs are device globals,
// referenced internally only).
// ---------------------------------------------------------------------------
__global__ __launch_bounds__(256) void prep_kernel(const float* __restrict__ x,
                                                   const float* __restrict__ wa,
                                                   const float* __restrict__ wp) {
    const int i4 = blockIdx.x * blockDim.x + threadIdx.x;   // 4 elems each
    const int i = i4 * 4;
    if (i < M_TOT * K_TOT) {
        float4 v = *(const float4*)(x + i);
        *(uint2*)(g_xh + i) = make_uint2(cvt2(v.x, v.y), cvt2(v.z, v.w));
    }
    if (i < K_TOT * 3 * E_) {
        float4 v = *(const float4*)(wa + i);
        *(uint2*)(g_wah + i) = make_uint2(cvt2(v.x, v.y), cvt2(v.z, v.w));
    }
    if (i < K_TOT * E_) {
        float4 v = *(const float4*)(wp + i);
        *(uint2*)(g_wph + i) = make_uint2(cvt2(v.x, v.y), cvt2(v.z, v.w));
    }
}

// ---------------------------------------------------------------------------
// fp16 mma.sync GEMM, fp16 operands, register-prefetch pipeline.
//   C[4096, N] = A[4096,1024] @ W[1024, N]  (+ bias)
// A/W selected in DEVICE code: EPI==0 -> g_xh/g_wah, EPI==1 -> g_yh/g_wph.
// CTA 128x128, BK=32, 256 threads (8 warps, 64x32 warp tiles), 16KB smem.
// ---------------------------------------------------------------------------
template <int EPI>
__global__ __launch_bounds__(256) void hgemm_kernel(
    const float* __restrict__ bias, float* __restrict__ Cout, int N) {
    __shared__ __align__(16) __half As[128 * 32];
    __shared__ __align__(16) __half Bs[32 * 128];

    const __half* A = (EPI == 1) ? g_yh : g_xh;
    const __half* W = (EPI == 1) ? g_wph : g_wah;

    const uint32_t aBase = s2u(As);
    const uint32_t bBase = s2u(Bs);
    const int tid = threadIdx.x;
    const int lane = tid & 31;
    const int warp = tid >> 5;
    const int wm = warp >> 2;
    const int wn = warp & 3;
    const int row0 = blockIdx.y * 128;
    const int col0 = blockIdx.x * 128;

    // A tile: 128 rows x 64B; chunk ids {tid, tid+256}: r=id>>2, c=id&3.
    const int ar = tid >> 2, ac = tid & 3;
    // B tile: 32 rows x 256B; chunk ids {tid, tid+256}: k=id>>4, c=id&15.
    const int bk = tid >> 4, bc = tid & 15;

    const __half* aP0 = A + (size_t)(row0 + ar) * K_TOT + ac * 8;
    const __half* aP1 = aP0 + (size_t)64 * K_TOT;
    const __half* bP0 = W + (size_t)bk * N + col0 + bc * 8;
    const __half* bP1 = bP0 + (size_t)16 * N;

    float acc[4][4][4];
#pragma unroll
    for (int i = 0; i < 4; ++i)
#pragma unroll
        for (int j = 0; j < 4; ++j)
#pragma unroll
            for (int k = 0; k < 4; ++k) acc[i][j][k] = 0.f;

    uint4 ra0 = *(const uint4*)(aP0);
    uint4 ra1 = *(const uint4*)(aP1);
    uint4 rb0 = *(const uint4*)(bP0);
    uint4 rb1 = *(const uint4*)(bP1);

    for (int kc = 0; kc < K_TOT / 32; ++kc) {
        __syncthreads();
        *(uint4*)((char*)As + ar * 64 + ((ac ^ (ar & 3)) << 4)) = ra0;
        *(uint4*)((char*)As + (ar + 64) * 64 + ((ac ^ (ar & 3)) << 4)) = ra1;
        *(uint4*)((char*)Bs + bk * 256 + ((bc ^ (bk & 7)) << 4)) = rb0;
        *(uint4*)((char*)Bs + (bk + 16) * 256 + ((bc ^ (bk & 7)) << 4)) = rb1;
        __syncthreads();

        if (kc + 1 < K_TOT / 32) {      // prefetch next tile under the mmas
            const int k0 = (kc + 1) * 32;
            ra0 = *(const uint4*)(aP0 + k0);
            ra1 = *(const uint4*)(aP1 + k0);
            rb0 = *(const uint4*)(bP0 + (size_t)k0 * N);
            rb1 = *(const uint4*)(bP1 + (size_t)k0 * N);
        }

#pragma unroll
        for (int ks = 0; ks < 2; ++ks) {
            uint32_t bf[4][2];
#pragma unroll
            for (int nt = 0; nt < 4; ++nt) {
                const int n0 = wn * 32 + nt * 8;
                const int l = lane & 15;
                const int krow = ks * 16 + (l >> 3) * 8 + (l & 7);
                ldsm_x2t(bf[nt], bBase + krow * 256 + (((n0 >> 3) ^ (krow & 7)) << 4));
            }
#pragma unroll
            for (int mt = 0; mt < 4; ++mt) {
                uint32_t af[4];
                const int mrow = wm * 64 + mt * 16 + (lane & 15);
                const int chnk = ks * 2 + (lane >> 4);
                ldsm_x4(af, aBase + mrow * 64 + ((chnk ^ (mrow & 3)) << 4));
#pragma unroll
                for (int nt = 0; nt < 4; ++nt) mma_f16(acc[mt][nt], af, bf[nt]);
            }
        }
    }

    // ---- epilogue ----
#pragma unroll
    for (int mt = 0; mt < 4; ++mt) {
#pragma unroll
        for (int nt = 0; nt < 4; ++nt) {
            const int m_base = row0 + wm * 64 + mt * 16 + (lane >> 2);
            const int n_base = col0 + wn * 32 + nt * 8 + (lane & 3) * 2;
#pragma unroll
            for (int e = 0; e < 4; ++e) {
                const int m = m_base + (e >> 1) * 8;
                const int n = n_base + (e & 1);
                const float v = acc[mt][nt][e] + __ldg(bias + n);
                if (EPI == 0) {
                    const int which = n >> 10;
                    const int ei = n & 1023;
                    const int h = ei >> 6;
                    const int d = ei & 63;
                    const int b = m >> 11;
                    const int t = m & 2047;
                    const size_t idx = (((size_t)(b * H_ + h) * T_ + t) << 6) + d;
                    if (which == 0)      g_qh[idx] = __float2half_rn(v * 0.125f);
                    else if (which == 1) g_kh[idx] = __float2half_rn(v);
                    else                 g_vh[idx] = __float2half_rn(v);
                } else {
                    Cout[(size_t)m * E_ + n] = v;
                }
            }
        }
    }
}

// ---------------------------------------------------------------------------
// Tensor-core causal flash attention (FA2, mma.sync fp16, fp32 softmax).
// 8 warps, 128-query tile (16 rows/warp), 64-key fp16 KV tiles in smem.
// ---------------------------------------------------------------------------
__global__ __launch_bounds__(256) void fattn_kernel() {
    __shared__ __align__(16) __half Ks[64 * 64];   // [key][d], swizzled
    __shared__ __align__(16) __half Vs[64 * 64];

    const int tid = threadIdx.x, lane = tid & 31, w = tid >> 5;
    const int q0 = blockIdx.x * 128;
    const int h = blockIdx.y, b = blockIdx.z;
    const size_t bh = (size_t)(b * H_ + h) * T_;
    const int wq = q0 + w * 16;
    const uint32_t ksB = s2u(Ks), vsB = s2u(Vs);

    // Q fragments: fp16 pairs are contiguous -> direct uint32 loads.
    uint32_t aq[4][4];
    {
        const __half* qr0 = g_qh + (bh + wq + (lane >> 2)) * D_;
        const __half* qr1 = qr0 + 8 * D_;
#pragma unroll
        for (int ks = 0; ks < 4; ++ks) {
            const int c = ks * 16 + (lane & 3) * 2;
            aq[ks][0] = *(const uint32_t*)(qr0 + c);
            aq[ks][1] = *(const uint32_t*)(qr1 + c);
            aq[ks][2] = *(const uint32_t*)(qr0 + c + 8);
            aq[ks][3] = *(const uint32_t*)(qr1 + c + 8);
        }
    }

    float o[8][4];
#pragma unroll
    for (int i = 0; i < 8; ++i)
#pragma unroll
        for (int e = 0; e < 4; ++e) o[i][e] = 0.f;
    float m0 = -1e30f, m1 = -1e30f, l0 = 0.f, l1 = 0.f;

    const int ntiles = 2 * blockIdx.x + 2;
    for (int kt = 0; kt < ntiles; ++kt) {
        __syncthreads();
        // 64x64 fp16 tile = 512 16B chunks each for K and V; 2/thread each.
#pragma unroll
        for (int i = 0; i < 2; ++i) {
            const int cid = i * 256 + tid;
            const int key = cid >> 3, ch = cid & 7;
            const uint4 ku = *(const uint4*)(g_kh + (bh + kt * 64 + key) * D_ + ch * 8);
            const uint4 vu = *(const uint4*)(g_vh + (bh + kt * 64 + key) * D_ + ch * 8);
            *(uint4*)((char*)Ks + key * 128 + ((ch ^ (key & 7)) << 4)) = ku;
            *(uint4*)((char*)Vs + key * 128 + ((ch ^ (key & 7)) << 4)) = vu;
        }
        __syncthreads();
        if (kt * 64 > wq + 15) continue;

        // ---- S = Q K^T ----
        float s[8][4];
#pragma unroll
        for (int nt = 0; nt < 8; ++nt)
#pragma unroll
            for (int e = 0; e < 4; ++e) s[nt][e] = 0.f;
#pragma unroll
        for (int p = 0; p < 2; ++p) {
#pragma unroll
            for (int nt = 0; nt < 8; ++nt) {
                uint32_t bk4[4];
                const int key = nt * 8 + (lane & 7);
                const int ch = p * 4 + (lane >> 3);
                ldsm_x4(bk4, ksB + key * 128 + ((ch ^ (key & 7)) << 4));
                mma_f16(s[nt], aq[2 * p], bk4);
                mma_f16(s[nt], aq[2 * p + 1], bk4 + 2);
            }
        }

        // ---- causal mask ----
        if (kt * 64 + 63 > wq) {
            const int r0a = wq + (lane >> 2);
            const int colb = kt * 64 + (lane & 3) * 2;
#pragma unroll
            for (int nt = 0; nt < 8; ++nt) {
                const int c0 = colb + nt * 8;
                if (c0 > r0a)         s[nt][0] = -1e30f;
                if (c0 + 1 > r0a)     s[nt][1] = -1e30f;
                if (c0 > r0a + 8)     s[nt][2] = -1e30f;
                if (c0 + 1 > r0a + 8) s[nt][3] = -1e30f;
            }
        }

        // ---- online softmax ----
        float mx0 = -1e30f, mx1 = -1e30f;
#pragma unroll
        for (int nt = 0; nt < 8; ++nt) {
            mx0 = fmaxf(mx0, fmaxf(s[nt][0], s[nt][1]));
            mx1 = fmaxf(mx1, fmaxf(s[nt][2], s[nt][3]));
        }
        mx0 = fmaxf(mx0, __shfl_xor_sync(0xffffffffu, mx0, 1));
        mx0 = fmaxf(mx0, __shfl_xor_sync(0xffffffffu, mx0, 2));
        mx1 = fmaxf(mx1, __shfl_xor_sync(0xffffffffu, mx1, 1));
        mx1 = fmaxf(mx1, __shfl_xor_sync(0xffffffffu, mx1, 2));
        const float mn0 = fmaxf(m0, mx0), mn1 = fmaxf(m1, mx1);
        const float sc0 = fexp(m0 - mn0), sc1 = fexp(m1 - mn1);
        m0 = mn0; m1 = mn1;
        float rs0 = 0.f, rs1 = 0.f;
#pragma unroll
        for (int nt = 0; nt < 8; ++nt) {
            s[nt][0] = fexp(s[nt][0] - mn0);
            s[nt][1] = fexp(s[nt][1] - mn0);
            s[nt][2] = fexp(s[nt][2] - mn1);
            s[nt][3] = fexp(s[nt][3] - mn1);
            rs0 += s[nt][0] + s[nt][1];
            rs1 += s[nt][2] + s[nt][3];
        }
        rs0 += __shfl_xor_sync(0xffffffffu, rs0, 1);
        rs0 += __shfl_xor_sync(0xffffffffu, rs0, 2);
        rs1 += __shfl_xor_sync(0xffffffffu, rs1, 1);
        rs1 += __shfl_xor_sync(0xffffffffu, rs1, 2);
        l0 = l0 * sc0 + rs0;
        l1 = l1 * sc1 + rs1;
#pragma unroll
        for (int nt = 0; nt < 8; ++nt) {
            o[nt][0] *= sc0; o[nt][1] *= sc0;
            o[nt][2] *= sc1; o[nt][3] *= sc1;
        }

        // ---- P -> A fragments ----
        uint32_t pa[4][4];
#pragma unroll
        for (int kp = 0; kp < 4; ++kp) {
            pa[kp][0] = cvt2(s[2 * kp][0],     s[2 * kp][1]);
            pa[kp][1] = cvt2(s[2 * kp][2],     s[2 * kp][3]);
            pa[kp][2] = cvt2(s[2 * kp + 1][0], s[2 * kp + 1][1]);
            pa[kp][3] = cvt2(s[2 * kp + 1][2], s[2 * kp + 1][3]);
        }

        // ---- O += P V ----
#pragma unroll
        for (int p2 = 0; p2 < 2; ++p2) {
#pragma unroll
            for (int nt2 = 0; nt2 < 8; ++nt2) {
                uint32_t bv[4];
                const int key = p2 * 32 + (lane >> 3) * 8 + (lane & 7);
                ldsm_x4t(bv, vsB + key * 128 + ((nt2 ^ (key & 7)) << 4));
                mma_f16(o[nt2], pa[2 * p2], bv);
                mma_f16(o[nt2], pa[2 * p2 + 1], bv + 2);
            }
        }
    }

    // ---- finalize + write y (fp16) ----
    const float inv0 = 1.f / l0, inv1 = 1.f / l1;
    __half* y0 = g_yh + ((size_t)(b * T_) + wq + (lane >> 2)) * E_ + h * D_ + (lane & 3) * 2;
    __half* y1 = y0 + 8 * E_;
#pragma unroll
    for (int nt = 0; nt < 8; ++nt) {
        *(uint32_t*)(y0 + nt * 8) = cvt2(o[nt][0] * inv0, o[nt][1] * inv0);
        *(uint32_t*)(y1 + nt * 8) = cvt2(o[nt][2] * inv1, o[nt][3] * inv1);
    }
}

// ---------------------------------------------------------------------------
// Launch: prep -> QKV GEMM -> attention -> projection GEMM.
// ---------------------------------------------------------------------------
extern "C" void kernel_launch(void* const* d_in, const int* in_sizes, int n_in,
                              void* d_out, int out_size) {
    const float* x      = (const float*)d_in[0];
    const float* W_attn = (const float*)d_in[1];
    const float* b_attn = (const float*)d_in[2];
    const float* W_proj = (const float*)d_in[3];
    const float* b_proj = (const float*)d_in[4];
    float* out = (float*)d_out;

    // 0) fp32 -> fp16 operand conversion
    prep_kernel<<<(M_TOT * K_TOT / 4 + 255) / 256, 256>>>(x, W_attn, W_proj);

    // 1) QKV = x @ W_attn + b_attn
    {
        dim3 grid(3 * E_ / 128, M_TOT / 128);
        hgemm_kernel<0><<<grid, 256>>>(b_attn, nullptr, 3 * E_);
    }
    // 2) causal attention -> g_yh
    {
        dim3 grid(T_ / 128, H_, B_);
        fattn_kernel<<<grid, 256>>>();
    }
    // 3) out = y @ W_proj + b_proj
    {
        dim3 grid(E_ / 128, M_TOT / 128);
        hgemm_kernel<1><<<grid, 256>>>(b_proj, out, E_);
    }
}